// round 14
// baseline (speedup 1.0000x reference)
#include <cuda_runtime.h>
#include <cuda_fp16.h>
#include <math.h>
#include <stdint.h>

// ---------------- problem constants ----------------
constexpr int Bn  = 8;
constexpr int Tt  = 16;
constexpr int Hh  = 14;
constexpr int Ww  = 14;
constexpr int D   = 768;
constexpr int NHh = 12;
constexpr int HID = 3072;
constexpr int Np  = Hh * Ww * Tt;      // 3136
constexpr int MT  = Bn * Np;           // 25088 (= 98*256)
constexpr int SSP = 1 + Hh * Ww;       // 197
constexpr int MS  = Bn * Tt * SSP;     // 25216
constexpr int MX  = Bn * (1 + Np);     // 25096
constexpr int MXP = 25216;
constexpr int MSP = 25344;             // pad to multiple of 256 for A-tile reads

// ---------------- scratch ----------------
__device__ float  g_xnc [MT * D];
__device__ __half g_lnh [MSP * D];       // padded (tail rows stay zero-init / stale-finite)
__device__ __half g_qkvh[MS * 3 * D];
__device__ __half g_atth[MSP * D];       // padded
__device__ float  g_xt2 [MT * D];
__device__ float  g_xnew[MX * D];
__device__ __half g_hidh[MSP * HID];     // padded
__device__ float  g_clsb[Bn * Tt * D];
__device__ float  g_bcomb[D];
// transposed-weight buffers
__device__ __half g_w_tqkv [3 * D * D];
__device__ __half g_w_comb [D * D];
__device__ __half g_w_tfc  [D * D];
__device__ __half g_projw_h[D * D];
__device__ __half g_w_sqkv [3 * D * D];
__device__ __half g_w_sproj[D * D];
__device__ __half g_w_fc1  [HID * D];
__device__ __half g_w_fc2  [D * HID];

// ---------------- PTX helpers ----------------
__device__ __forceinline__ uint32_t smem_u32(const void* p) {
    uint32_t a;
    asm("{ .reg .u64 t; cvta.to.shared.u64 t, %1; cvt.u32.u64 %0, t; }" : "=r"(a) : "l"(p));
    return a;
}
__device__ __forceinline__ float gelu_exact(float v) {
    return 0.5f * v * (1.0f + erff(v * 0.70710678118654752440f));
}
__device__ __forceinline__ uint32_t pack_h2(float a, float b) {
    __half2 h = __floats2half2_rn(a, b);
    return *reinterpret_cast<uint32_t*>(&h);
}

#define CP_ASYNC16(dst, src) \
    asm volatile("cp.async.cg.shared.global [%0], [%1], 16;" :: "r"(dst), "l"(src) : "memory")
#define CP_COMMIT() asm volatile("cp.async.commit_group;" ::: "memory")
#define CP_WAIT0()  asm volatile("cp.async.wait_group 0;" ::: "memory")
#define CP_WAIT1()  asm volatile("cp.async.wait_group 1;" ::: "memory")

#define LDSM4(r, addr) \
    asm volatile("ldmatrix.sync.aligned.m8n8.x4.shared.b16 {%0,%1,%2,%3}, [%4];" \
        : "=r"((r)[0]), "=r"((r)[1]), "=r"((r)[2]), "=r"((r)[3]) : "r"(addr))
#define LDSM4T(r, addr) \
    asm volatile("ldmatrix.sync.aligned.m8n8.x4.trans.shared.b16 {%0,%1,%2,%3}, [%4];" \
        : "=r"((r)[0]), "=r"((r)[1]), "=r"((r)[2]), "=r"((r)[3]) : "r"(addr))

#define MMA16816(c, a, b0, b1) \
    asm volatile("mma.sync.aligned.m16n8k16.row.col.f32.f16.f16.f32 " \
        "{%0,%1,%2,%3}, {%4,%5,%6,%7}, {%8,%9}, {%0,%1,%2,%3};" \
        : "+f"((c)[0]), "+f"((c)[1]), "+f"((c)[2]), "+f"((c)[3]) \
        : "r"((a)[0]), "r"((a)[1]), "r"((a)[2]), "r"((a)[3]), "r"(b0), "r"(b1))

// ---------------- combined weight transpose ----------------
struct TransJob { const float* W; __half* Wt; int K, N, tile0; };
struct TransJobs { TransJob j[6]; int total; };

__global__ void transpose_all(TransJobs jobs) {
    __shared__ float tile[32][33];
    int t = blockIdx.x;
    int ji = 0;
    #pragma unroll
    for (int i = 1; i < 6; i++) if (t >= jobs.j[i].tile0) ji = i;
    const TransJob& J = jobs.j[ji];
    int lt = t - J.tile0;
    int ktiles = J.K / 32;
    int k0 = (lt % ktiles) * 32, n0 = (lt / ktiles) * 32;
    int tx = threadIdx.x, ty = threadIdx.y;  // 32 x 8
    for (int r = ty; r < 32; r += 8) tile[r][tx] = J.W[(size_t)(k0 + r) * J.N + n0 + tx];
    __syncthreads();
    for (int r = ty; r < 32; r += 8) J.Wt[(size_t)(n0 + r) * J.K + k0 + tx] = __float2half_rn(tile[tx][r]);
}

__global__ void copyround_h(const float* __restrict__ W, __half* __restrict__ Wh, int n) {
    int i = blockIdx.x * blockDim.x + threadIdx.x;
    if (i < n) Wh[i] = __float2half_rn(W[i]);
}

// bcomb[n] = sum_j proj_b[j] * tfc_w[j,n] + tfc_b[n]  — warp per n
__global__ void bias_comb(const float* __restrict__ proj_b, const float* __restrict__ tfc_w,
                          const float* __restrict__ tfc_b, float* __restrict__ bcomb) {
    int warp = (blockIdx.x * blockDim.x + threadIdx.x) >> 5;
    int lane = threadIdx.x & 31;
    if (warp >= D) return;
    float s = 0.f;
    for (int j = lane; j < D; j += 32) s += proj_b[j] * tfc_w[(size_t)j * D + warp];
    #pragma unroll
    for (int o = 16; o; o >>= 1) s += __shfl_xor_sync(0xffffffffu, s, o);
    if (lane == 0) bcomb[warp] = s + tfc_b[warp];
}

// ---------------- fp16 tensor-core GEMM: CTA 256x128, warp 64x64 ----------------
// EPI: 0=none 1=+bias 2=+bias+residual 3=+bias+gelu
//      4=+bias, scatter x_new build (see R12 comment)
constexpr int TILE_A    = 256 * 128;        // 32KB per stage (A)
constexpr int TILE_BB   = 128 * 128;        // 16KB per stage (B)
constexpr int STAGE_B   = TILE_A + TILE_BB; // 48KB
constexpr int GS        = 3;
constexpr int GEMM_SMEM = GS * STAGE_B;     // 147456

template <int EPI, typename TO>
__global__ void __launch_bounds__(256, 1) gemm_hmma(
    int Mreal, int N, int K,
    const __half* __restrict__ A, const __half* __restrict__ Bt,
    const float* __restrict__ bias, const float* __restrict__ Res,
    TO* __restrict__ C, float* __restrict__ Aux)
{
    extern __shared__ char smbuf[];
    const uint32_t sb = smem_u32(smbuf);
    const int tid  = threadIdx.x;
    const int wid  = tid >> 5, lane = tid & 31;
    const int wm   = wid & 3,  wn   = wid >> 2;     // 4(M) x 2(N), warp tile 64x64
    const int n0   = blockIdx.x * 128, m0 = blockIdx.y * 256;

    auto load_stage = [&](int chunk, int st) {
        uint32_t base = sb + st * STAGE_B;
        const __half* asrc = A  + (size_t)m0 * K + chunk * 64;
        const __half* bsrc = Bt + (size_t)n0 * K + chunk * 64;
        #pragma unroll
        for (int i = 0; i < 8; i++) {          // A: 256 rows x 8 chunks
            int idx = tid + i * 256;
            int r = idx >> 3, c = idx & 7;
            uint32_t sw = (uint32_t)((c ^ (r & 7)) << 4);
            CP_ASYNC16(base + r * 128 + sw, asrc + (size_t)r * K + c * 8);
        }
        #pragma unroll
        for (int i = 0; i < 4; i++) {          // B: 128 rows x 8 chunks
            int idx = tid + i * 256;
            int r = idx >> 3, c = idx & 7;
            uint32_t sw = (uint32_t)((c ^ (r & 7)) << 4);
            CP_ASYNC16(base + TILE_A + r * 128 + sw, bsrc + (size_t)r * K + c * 8);
        }
    };

    const int NC = K / 64;
    load_stage(0, 0); CP_COMMIT();
    load_stage(1, 1); CP_COMMIT();

    float acc[4][8][4];
    #pragma unroll
    for (int i = 0; i < 4; i++)
        #pragma unroll
        for (int j = 0; j < 8; j++)
            #pragma unroll
            for (int q = 0; q < 4; q++) acc[i][j][q] = 0.f;

    const int fr = lane & 15;
    const uint32_t xr    = (uint32_t)(fr & 7);
    const uint32_t aterm = (wm * 64 + fr) * 128;
    const uint32_t bterm = (wn * 64 + fr) * 128;
    const uint32_t csel  = (lane >> 4) & 1;

    for (int i = 0; i < NC; i++) {
        if (i == NC - 1) CP_WAIT0(); else CP_WAIT1();
        __syncthreads();
        if (i + 2 < NC) { load_stage(i + 2, (i + 2) % GS); CP_COMMIT(); }

        uint32_t As = sb + (i % GS) * STAGE_B;
        uint32_t Bs = As + TILE_A;

        #pragma unroll
        for (int ks = 0; ks < 4; ks++) {
            uint32_t c  = ks * 2 + csel;
            uint32_t sw = ((c ^ xr) << 4);
            uint32_t a[4][4];
            #pragma unroll
            for (int mt = 0; mt < 4; mt++)
                LDSM4(a[mt], As + aterm + mt * 2048 + sw);
            uint32_t bf[4][4];
            #pragma unroll
            for (int p = 0; p < 4; p++)
                LDSM4(bf[p], Bs + bterm + p * 2048 + sw);
            #pragma unroll
            for (int mt = 0; mt < 4; mt++)
                #pragma unroll
                for (int nt = 0; nt < 8; nt++) {
                    uint32_t b0 = bf[nt >> 1][nt & 1];
                    uint32_t b1 = bf[nt >> 1][(nt & 1) + 2];
                    MMA16816(acc[mt][nt], a[mt], b0, b1);
                }
        }
    }

    const int rbase = m0 + wm * 64 + (lane >> 2);
    const int cbase = n0 + wn * 64 + (lane & 3) * 2;
    #pragma unroll
    for (int mt = 0; mt < 4; mt++) {
        #pragma unroll
        for (int half_r = 0; half_r < 2; half_r++) {
            int row = rbase + mt * 16 + half_r * 8;
            if (row >= Mreal) continue;
            if (EPI == 4) {
                int bt = row / SSP, j = row % SSP;
                int b = bt >> 4, t = bt & 15;
                if (j == 0) {
                    float* dst = Aux + (size_t)bt * D;
                    #pragma unroll
                    for (int nt = 0; nt < 8; nt++) {
                        int col = cbase + nt * 8;
                        float v0 = acc[mt][nt][half_r * 2 + 0] + __ldg(&bias[col]);
                        float v1 = acc[mt][nt][half_r * 2 + 1] + __ldg(&bias[col + 1]);
                        *(float2*)(dst + col) = make_float2(v0, v1);
                    }
                } else {
                    int n = (j - 1) * Tt + t;
                    const float* rsrc = Res + (size_t)(b * Np + n) * D;
                    float* dst = (float*)C + (size_t)(b * (1 + Np) + 1 + n) * D;
                    #pragma unroll
                    for (int nt = 0; nt < 8; nt++) {
                        int col = cbase + nt * 8;
                        const float2 rv = *(const float2*)(rsrc + col);
                        float v0 = acc[mt][nt][half_r * 2 + 0] + __ldg(&bias[col]) + rv.x;
                        float v1 = acc[mt][nt][half_r * 2 + 1] + __ldg(&bias[col + 1]) + rv.y;
                        *(float2*)(dst + col) = make_float2(v0, v1);
                    }
                }
            } else {
                #pragma unroll
                for (int nt = 0; nt < 8; nt++) {
                    int col = cbase + nt * 8;
                    float v0 = acc[mt][nt][half_r * 2 + 0];
                    float v1 = acc[mt][nt][half_r * 2 + 1];
                    if (EPI >= 1) { v0 += __ldg(&bias[col]); v1 += __ldg(&bias[col + 1]); }
                    if (EPI == 2) {
                        const float2 rv = *(const float2*)(Res + (size_t)row * N + col);
                        v0 += rv.x; v1 += rv.y;
                    }
                    if (EPI == 3) { v0 = gelu_exact(v0); v1 = gelu_exact(v1); }
                    if (sizeof(TO) == 2) {
                        *(__half2*)((__half*)C + (size_t)row * N + col) = __floats2half2_rn(v0, v1);
                    } else {
                        *(float2*)((float*)C + (size_t)row * N + col) = make_float2(v0, v1);
                    }
                }
            }
        }
    }
}

// ---------------- warp-per-row LayerNorm core ----------------
__device__ __forceinline__ void ln_warp(const float4 v[6],
                                        const float* __restrict__ w,
                                        const float* __restrict__ bvec,
                                        __half* __restrict__ dst, int lane) {
    float s = 0.f, ss = 0.f;
    #pragma unroll
    for (int i = 0; i < 6; i++) {
        s  += v[i].x + v[i].y + v[i].z + v[i].w;
        ss += v[i].x * v[i].x + v[i].y * v[i].y + v[i].z * v[i].z + v[i].w * v[i].w;
    }
    #pragma unroll
    for (int o = 16; o; o >>= 1) {
        s  += __shfl_xor_sync(0xffffffffu, s,  o);
        ss += __shfl_xor_sync(0xffffffffu, ss, o);
    }
    float mean = s * (1.0f / 768.0f);
    float var  = ss * (1.0f / 768.0f) - mean * mean;
    float rstd = rsqrtf(var + 1e-5f);
    #pragma unroll
    for (int i = 0; i < 6; i++) {
        int c4 = (lane + 32 * i) * 4;
        float4 wv = *(const float4*)(w + c4);
        float4 bv = *(const float4*)(bvec + c4);
        float o0 = (v[i].x - mean) * rstd * wv.x + bv.x;
        float o1 = (v[i].y - mean) * rstd * wv.y + bv.y;
        float o2 = (v[i].z - mean) * rstd * wv.z + bv.z;
        float o3 = (v[i].w - mean) * rstd * wv.w + bv.w;
        uint2 pk = make_uint2(pack_h2(o0, o1), pack_h2(o2, o3));
        *(uint2*)(dst + c4) = pk;
    }
}

__global__ void ln_gather_t(const float* __restrict__ x,
                            const float* __restrict__ w, const float* __restrict__ bvec,
                            float* __restrict__ xnc, __half* __restrict__ lnh) {
    int row = blockIdx.x * 8 + (threadIdx.x >> 5);
    int lane = threadIdx.x & 31;
    if (row >= MT) return;
    int b = row / Np, n = row % Np;
    const float4* src4 = (const float4*)(x + (size_t)(b * (1 + Np) + 1 + n) * D);
    float4 v[6];
    #pragma unroll
    for (int i = 0; i < 6; i++) v[i] = src4[lane + 32 * i];
    float4* dstx = (float4*)(xnc + (size_t)row * D);
    #pragma unroll
    for (int i = 0; i < 6; i++) dstx[lane + 32 * i] = v[i];
    ln_warp(v, w, bvec, lnh + (size_t)row * D, lane);
}

__global__ void ln_xs_kernel(const float* __restrict__ x,
                             const float* __restrict__ xt2,
                             const float* __restrict__ w, const float* __restrict__ bvec,
                             __half* __restrict__ lnh) {
    int row = blockIdx.x * 8 + (threadIdx.x >> 5);
    int lane = threadIdx.x & 31;
    if (row >= MS) return;
    int bt = row / SSP, j = row % SSP;
    int b = bt >> 4, t = bt & 15;
    const float* src = (j == 0)
        ? (x + (size_t)b * (1 + Np) * D)
        : (xt2 + (size_t)(b * Np + (j - 1) * Tt + t) * D);
    const float4* src4 = (const float4*)src;
    float4 v[6];
    #pragma unroll
    for (int i = 0; i < 6; i++) v[i] = src4[lane + 32 * i];
    ln_warp(v, w, bvec, lnh + (size_t)row * D, lane);
}

// final LN over x_new; p>0 rows already complete (EPI4 GEMM); p==0 assembled here.
__global__ void ln_build(const float* __restrict__ x,
                         const float* __restrict__ xnew_in,
                         const float* __restrict__ clsb,
                         const float* __restrict__ w, const float* __restrict__ bvec,
                         float* __restrict__ xnew, __half* __restrict__ lnh) {
    int row = blockIdx.x * 8 + (threadIdx.x >> 5);
    int lane = threadIdx.x & 31;
    if (row >= MX) return;
    int b = row / (1 + Np), p = row % (1 + Np);
    float4 v[6];
    if (p == 0) {
        const float4* a4 = (const float4*)(x + (size_t)row * D);
        #pragma unroll
        for (int i = 0; i < 6; i++) {
            float4 a = a4[lane + 32 * i];
            float4 c = make_float4(0.f, 0.f, 0.f, 0.f);
            for (int t = 0; t < Tt; t++) {
                const float4* r4 = (const float4*)(clsb + (size_t)(b * Tt + t) * D);
                float4 r = r4[lane + 32 * i];
                c.x += r.x; c.y += r.y; c.z += r.z; c.w += r.w;
            }
            const float inv16 = 1.0f / 16.0f;
            v[i] = make_float4(a.x + c.x * inv16, a.y + c.y * inv16,
                               a.z + c.z * inv16, a.w + c.w * inv16);
        }
        float4* dx = (float4*)(xnew + (size_t)row * D);
        #pragma unroll
        for (int i = 0; i < 6; i++) dx[lane + 32 * i] = v[i];
    } else {
        const float4* a4 = (const float4*)(xnew_in + (size_t)row * D);
        #pragma unroll
        for (int i = 0; i < 6; i++) v[i] = a4[lane + 32 * i];
    }
    ln_warp(v, w, bvec, lnh + (size_t)row * D, lane);
}

// ---------------- temporal attention: tensor-core, warp per (R,h) ----------------
__global__ void __launch_bounds__(128) attn_t_mma(const __half* __restrict__ qkv,
                                                  __half* __restrict__ out) {
    __shared__ char sm[4 * 6144];
    const int warp = threadIdx.x >> 5, lane = threadIdx.x & 31;
    const int R = blockIdx.x;
    const int h = blockIdx.y * 4 + warp;
    const uint32_t sQ = smem_u32(sm) + warp * 6144;
    const uint32_t sK = sQ + 2048;
    const uint32_t sV = sQ + 4096;

    const __half* base = qkv + (size_t)(R * 16) * (3 * D) + h * 64;
    #pragma unroll
    for (int i = 0; i < 4; i++) {
        int idx = lane + i * 32;
        int r = idx >> 3, c = idx & 7;
        uint32_t sw = r * 128 + ((c ^ (r & 7)) << 4);
        const __half* rp = base + (size_t)r * (3 * D) + c * 8;
        CP_ASYNC16(sQ + sw, rp);
        CP_ASYNC16(sK + sw, rp + D);
        CP_ASYNC16(sV + sw, rp + 2 * D);
    }
    CP_COMMIT(); CP_WAIT0();
    __syncwarp();

    const uint32_t csel = (lane >> 4) & 1;
    const int fr = lane & 15;
    const uint32_t fterm = fr * 128, fxr = fr & 7;

    uint32_t aq[4][4];
    float s[2][4] = {};
    #pragma unroll
    for (int kc = 0; kc < 4; kc++) {
        uint32_t c = kc * 2 + csel;
        LDSM4(aq[kc], sQ + fterm + ((c ^ fxr) << 4));
        uint32_t bf[4];
        LDSM4(bf, sK + fterm + ((c ^ fxr) << 4));
        MMA16816(s[0], aq[kc], bf[0], bf[2]);
        MMA16816(s[1], aq[kc], bf[1], bf[3]);
    }

    const float scale = 0.125f;
    #pragma unroll
    for (int t = 0; t < 2; t++)
        #pragma unroll
        for (int q = 0; q < 4; q++) s[t][q] *= scale;
    float mx0 = fmaxf(fmaxf(s[0][0], s[0][1]), fmaxf(s[1][0], s[1][1]));
    float mx1 = fmaxf(fmaxf(s[0][2], s[0][3]), fmaxf(s[1][2], s[1][3]));
    #pragma unroll
    for (int o = 1; o <= 2; o <<= 1) {
        mx0 = fmaxf(mx0, __shfl_xor_sync(0xffffffffu, mx0, o));
        mx1 = fmaxf(mx1, __shfl_xor_sync(0xffffffffu, mx1, o));
    }
    float sum0 = 0.f, sum1 = 0.f;
    #pragma unroll
    for (int t = 0; t < 2; t++) {
        s[t][0] = __expf(s[t][0] - mx0); sum0 += s[t][0];
        s[t][1] = __expf(s[t][1] - mx0); sum0 += s[t][1];
        s[t][2] = __expf(s[t][2] - mx1); sum1 += s[t][2];
        s[t][3] = __expf(s[t][3] - mx1); sum1 += s[t][3];
    }
    #pragma unroll
    for (int o = 1; o <= 2; o <<= 1) {
        sum0 += __shfl_xor_sync(0xffffffffu, sum0, o);
        sum1 += __shfl_xor_sync(0xffffffffu, sum1, o);
    }
    float inv0 = 1.0f / sum0, inv1 = 1.0f / sum1;

    uint32_t pa[4];
    pa[0] = pack_h2(s[0][0], s[0][1]);
    pa[1] = pack_h2(s[0][2], s[0][3]);
    pa[2] = pack_h2(s[1][0], s[1][1]);
    pa[3] = pack_h2(s[1][2], s[1][3]);

    float o[8][4] = {};
    #pragma unroll
    for (int dt2 = 0; dt2 < 4; dt2++) {
        uint32_t c = dt2 * 2 + csel;
        uint32_t vf[4];
        LDSM4T(vf, sV + fterm + ((c ^ fxr) << 4));
        MMA16816(o[2 * dt2],     pa, vf[0], vf[1]);
        MMA16816(o[2 * dt2 + 1], pa, vf[2], vf[3]);
    }

    int r0 = lane >> 2;
    #pragma unroll
    for (int dt = 0; dt < 8; dt++) {
        int col = h * 64 + dt * 8 + (lane & 3) * 2;
        *(__half2*)(out + (size_t)(R * 16 + r0) * D + col) =
            __floats2half2_rn(o[dt][0] * inv0, o[dt][1] * inv0);
        *(__half2*)(out + (size_t)(R * 16 + r0 + 8) * D + col) =
            __floats2half2_rn(o[dt][2] * inv1, o[dt][3] * inv1);
    }
}

// ---------------- spatial attention: tensor-core FA2-style ----------------
constexpr int Lp = 208;
constexpr int ATTN_SMEM = Lp * 128 * 2 + 64 * 128;

__global__ void __launch_bounds__(128) attn_s_mma(const __half* __restrict__ qkv,
                                                  __half* __restrict__ out) {
    int bt = blockIdx.x, h = blockIdx.y;
    extern __shared__ char sm[];
    const uint32_t sK = smem_u32(sm);
    const uint32_t sV = sK + Lp * 128;
    const uint32_t sQ = sV + Lp * 128;
    const int tid = threadIdx.x, warp = tid >> 5, lane = tid & 31;

    const __half* base = qkv + (size_t)bt * SSP * (3 * D) + h * 64;

    for (int idx = tid; idx < 11 * 8; idx += 128) {
        int r = 197 + (idx >> 3), c = idx & 7;
        uint32_t sw = r * 128 + ((c ^ (r & 7)) << 4);
        *(uint4*)(sm + sw) = make_uint4(0, 0, 0, 0);
        *(uint4*)(sm + Lp * 128 + sw) = make_uint4(0, 0, 0, 0);
    }
    for (int idx = tid; idx < 197 * 8; idx += 128) {
        int r = idx >> 3, c = idx & 7;
        uint32_t sw = r * 128 + ((c ^ (r & 7)) << 4);
        CP_ASYNC16(sK + sw, base + (size_t)r * (3 * D) + D + c * 8);
        CP_ASYNC16(sV + sw, base + (size_t)r * (3 * D) + 2 * D + c * 8);
    }
    CP_COMMIT();

    const uint32_t csel = (lane >> 4) & 1;
    const float scale = 0.125f;

    for (int qt = 0; qt < 4; qt++) {
        int q0 = qt * 64;
        __syncthreads();
        for (int idx = tid; idx < 64 * 8; idx += 128) {
            int r = idx >> 3, c = idx & 7;
            int gr = min(q0 + r, 196);
            uint32_t sw = r * 128 + ((c ^ (r & 7)) << 4);
            CP_ASYNC16(sQ + sw, base + (size_t)gr * (3 * D) + c * 8);
        }
        CP_COMMIT(); CP_WAIT0();
        __syncthreads();

        if (q0 + warp * 16 >= SSP) continue;

        uint32_t aq[4][4];
        {
            int arow = warp * 16 + (lane & 15);
            uint32_t aterm = arow * 128, axr = arow & 7;
            #pragma unroll
            for (int kc = 0; kc < 4; kc++) {
                uint32_t c = kc * 2 + csel;
                LDSM4(aq[kc], sQ + aterm + ((c ^ axr) << 4));
            }
        }

        float s[26][4];
        #pragma unroll
        for (int t = 0; t < 26; t++)
            #pragma unroll
            for (int q = 0; q < 4; q++) s[t][q] = 0.f;

        for (int nt2 = 0; nt2 < 13; nt2++) {
            int brow = nt2 * 16 + (lane & 15);
            uint32_t bterm = brow * 128, bxr = brow & 7;
            #pragma unroll
            for (int kc = 0; kc < 4; kc++) {
                uint32_t c = kc * 2 + csel;
                uint32_t bf[4];
                LDSM4(bf, sK + bterm + ((c ^ bxr) << 4));
                MMA16816(s[2 * nt2],     aq[kc], bf[0], bf[2]);
                MMA16816(s[2 * nt2 + 1], aq[kc], bf[1], bf[3]);
            }
        }

        float mx0 = -1e30f, mx1 = -1e30f;
        #pragma unroll
        for (int t = 0; t < 26; t++) {
            int col = t * 8 + (lane & 3) * 2;
            if (col     >= 197) { s[t][0] = -1e30f; s[t][2] = -1e30f; } else { s[t][0] *= scale; s[t][2] *= scale; }
            if (col + 1 >= 197) { s[t][1] = -1e30f; s[t][3] = -1e30f; } else { s[t][1] *= scale; s[t][3] *= scale; }
            mx0 = fmaxf(mx0, fmaxf(s[t][0], s[t][1]));
            mx1 = fmaxf(mx1, fmaxf(s[t][2], s[t][3]));
        }
        #pragma unroll
        for (int o = 1; o <= 2; o <<= 1) {
            mx0 = fmaxf(mx0, __shfl_xor_sync(0xffffffffu, mx0, o));
            mx1 = fmaxf(mx1, __shfl_xor_sync(0xffffffffu, mx1, o));
        }
        float sum0 = 0.f, sum1 = 0.f;
        #pragma unroll
        for (int t = 0; t < 26; t++) {
            s[t][0] = __expf(s[t][0] - mx0); sum0 += s[t][0];
            s[t][1] = __expf(s[t][1] - mx0); sum0 += s[t][1];
            s[t][2] = __expf(s[t][2] - mx1); sum1 += s[t][2];
            s[t][3] = __expf(s[t][3] - mx1); sum1 += s[t][3];
        }
        #pragma unroll
        for (int o = 1; o <= 2; o <<= 1) {
            sum0 += __shfl_xor_sync(0xffffffffu, sum0, o);
            sum1 += __shfl_xor_sync(0xffffffffu, sum1, o);
        }
        float inv0 = 1.0f / sum0, inv1 = 1.0f / sum1;

        uint32_t pa[13][4];
        #pragma unroll
        for (int k = 0; k < 13; k++) {
            pa[k][0] = pack_h2(s[2 * k][0],     s[2 * k][1]);
            pa[k][1] = pack_h2(s[2 * k][2],     s[2 * k][3]);
            pa[k][2] = pack_h2(s[2 * k + 1][0], s[2 * k + 1][1]);
            pa[k][3] = pack_h2(s[2 * k + 1][2], s[2 * k + 1][3]);
        }

        float o[8][4];
        #pragma unroll
        for (int t = 0; t < 8; t++)
            #pragma unroll
            for (int q = 0; q < 4; q++) o[t][q] = 0.f;

        for (int kc = 0; kc < 13; kc++) {
            int vrow = kc * 16 + (lane & 15);
            uint32_t vterm = vrow * 128, vxr = vrow & 7;
            #pragma unroll
            for (int dt2 = 0; dt2 < 4; dt2++) {
                uint32_t c = dt2 * 2 + csel;
                uint32_t vf[4];
                LDSM4T(vf, sV + vterm + ((c ^ vxr) << 4));
                MMA16816(o[2 * dt2],     pa[kc], vf[0], vf[1]);
                MMA16816(o[2 * dt2 + 1], pa[kc], vf[2], vf[3]);
            }
        }

        int r0 = q0 + warp * 16 + (lane >> 2);
        #pragma unroll
        for (int dt = 0; dt < 8; dt++) {
            int col = h * 64 + dt * 8 + (lane & 3) * 2;
            if (r0 < 197)
                *(__half2*)(out + (size_t)(bt * SSP + r0) * D + col) =
                    __floats2half2_rn(o[dt][0] * inv0, o[dt][1] * inv0);
            if (r0 + 8 < 197)
                *(__half2*)(out + (size_t)(bt * SSP + r0 + 8) * D + col) =
                    __floats2half2_rn(o[dt][2] * inv1, o[dt][3] * inv1);
        }
    }
}

// ---------------- launch ----------------
extern "C" void kernel_launch(void* const* d_in, const int* in_sizes, int n_in,
                              void* d_out, int out_size) {
    const float* x        = (const float*)d_in[0];
    const float* tn1_w    = (const float*)d_in[1];
    const float* tn1_b    = (const float*)d_in[2];
    const float* t_qkv_w  = (const float*)d_in[3];
    const float* t_proj_w = (const float*)d_in[4];
    const float* t_proj_b = (const float*)d_in[5];
    const float* tfc_w    = (const float*)d_in[6];
    const float* tfc_b    = (const float*)d_in[7];
    const float* n1_w     = (const float*)d_in[8];
    const float* n1_b     = (const float*)d_in[9];
    const float* s_qkv_w  = (const float*)d_in[10];
    const float* s_proj_w = (const float*)d_in[11];
    const float* s_proj_b = (const float*)d_in[12];
    const float* n2_w     = (const float*)d_in[13];
    const float* n2_b     = (const float*)d_in[14];
    const float* fc1_w    = (const float*)d_in[15];
    const float* fc1_b    = (const float*)d_in[16];
    const float* fc2_w    = (const float*)d_in[17];
    const float* fc2_b    = (const float*)d_in[18];
    float* out = (float*)d_out;

    float  *p_xnc, *p_xt2, *p_xnew, *p_clsb, *p_bcomb;
    __half *p_lnh, *p_qkvh, *p_atth, *p_hidh;
    __half *w_tqkv, *w_comb, *w_tfc, *w_projh, *w_sqkv, *w_sproj, *w_fc1, *w_fc2;
    cudaGetSymbolAddress((void**)&p_xnc,  g_xnc);
    cudaGetSymbolAddress((void**)&p_lnh,  g_lnh);
    cudaGetSymbolAddress((void**)&p_qkvh, g_qkvh);
    cudaGetSymbolAddress((void**)&p_atth, g_atth);
    cudaGetSymbolAddress((void**)&p_xt2,  g_xt2);
    cudaGetSymbolAddress((void**)&p_xnew, g_xnew);
    cudaGetSymbolAddress((void**)&p_hidh, g_hidh);
    cudaGetSymbolAddress((void**)&p_clsb, g_clsb);
    cudaGetSymbolAddress((void**)&p_bcomb,g_bcomb);
    cudaGetSymbolAddress((void**)&w_tqkv, g_w_tqkv);
    cudaGetSymbolAddress((void**)&w_comb, g_w_comb);
    cudaGetSymbolAddress((void**)&w_tfc,  g_w_tfc);
    cudaGetSymbolAddress((void**)&w_projh,g_projw_h);
    cudaGetSymbolAddress((void**)&w_sqkv, g_w_sqkv);
    cudaGetSymbolAddress((void**)&w_sproj,g_w_sproj);
    cudaGetSymbolAddress((void**)&w_fc1,  g_w_fc1);
    cudaGetSymbolAddress((void**)&w_fc2,  g_w_fc2);

    cudaFuncSetAttribute(attn_s_mma, cudaFuncAttributeMaxDynamicSharedMemorySize, ATTN_SMEM);
    cudaFuncSetAttribute(gemm_hmma<0, __half>, cudaFuncAttributeMaxDynamicSharedMemorySize, GEMM_SMEM);
    cudaFuncSetAttribute(gemm_hmma<2, float >, cudaFuncAttributeMaxDynamicSharedMemorySize, GEMM_SMEM);
    cudaFuncSetAttribute(gemm_hmma<3, __half>, cudaFuncAttributeMaxDynamicSharedMemorySize, GEMM_SMEM);
    cudaFuncSetAttribute(gemm_hmma<4, float >, cudaFuncAttributeMaxDynamicSharedMemorySize, GEMM_SMEM);

    // side stream + events for prologue overlap
    static cudaStream_t s2 = nullptr;
    static cudaEvent_t evFork = nullptr, evJoin = nullptr;
    if (!s2) {
        cudaStreamCreateWithFlags(&s2, cudaStreamNonBlocking);
        cudaEventCreateWithFlags(&evFork, cudaEventDisableTiming);
        cudaEventCreateWithFlags(&evJoin, cudaEventDisableTiming);
    }

    // 0) weight transposes (one launch)
    TransJobs jobs;
    auto mkjob = [](const float* W, __half* Wt, int K, int N, int tile0) {
        TransJob j; j.W = W; j.Wt = Wt; j.K = K; j.N = N; j.tile0 = tile0; return j;
    };
    int t0 = 0;
    jobs.j[0] = mkjob(t_qkv_w, w_tqkv, D,   3 * D, t0); t0 += (D / 32) * (3 * D / 32);
    jobs.j[1] = mkjob(tfc_w,   w_tfc,  D,   D,     t0); t0 += (D / 32) * (D / 32);
    jobs.j[2] = mkjob(s_qkv_w, w_sqkv, D,   3 * D, t0); t0 += (D / 32) * (3 * D / 32);
    jobs.j[3] = mkjob(s_proj_w,w_sproj,D,   D,     t0); t0 += (D / 32) * (D / 32);
    jobs.j[4] = mkjob(fc1_w,   w_fc1,  D,   HID,   t0); t0 += (D / 32) * (HID / 32);
    jobs.j[5] = mkjob(fc2_w,   w_fc2,  HID, D,     t0); t0 += (HID / 32) * (D / 32);
    jobs.total = t0;
    transpose_all<<<t0, dim3(32, 8)>>>(jobs);

    // fork: composite-weight chain on s2
    cudaEventRecord(evFork, 0);
    cudaStreamWaitEvent(s2, evFork, 0);
    copyround_h<<<(D * D + 255) / 256, 256, 0, s2>>>(t_proj_w, w_projh, D * D);
    gemm_hmma<0, __half><<<dim3(D / 128, D / 256), 256, GEMM_SMEM, s2>>>(D, D, D, w_tfc, w_projh, nullptr, nullptr, w_comb, nullptr);
    bias_comb<<<(D * 32 + 255) / 256, 256, 0, s2>>>(t_proj_b, tfc_w, tfc_b, p_bcomb);
    cudaEventRecord(evJoin, s2);

    // 1) gather + temporal LN
    ln_gather_t<<<(MT + 7) / 8, 256>>>(x, tn1_w, tn1_b, p_xnc, p_lnh);

    // 2) temporal qkv -> half
    gemm_hmma<0, __half><<<dim3(3 * D / 128, MT / 256), 256, GEMM_SMEM>>>(MT, 3 * D, D, p_lnh, w_tqkv, nullptr, nullptr, p_qkvh, nullptr);

    // 3) temporal attention -> half
    attn_t_mma<<<dim3(Bn * Hh * Ww, 3), 128>>>(p_qkvh, p_atth);

    // join before using w_comb / bcomb
    cudaStreamWaitEvent(0, evJoin, 0);

    // 4) combined proj+tfc + residual(xnc) -> xt2 fp32
    gemm_hmma<2, float><<<dim3(D / 128, MT / 256), 256, GEMM_SMEM>>>(MT, D, D, p_atth, w_comb, p_bcomb, p_xnc, p_xt2, nullptr);

    // 5) spatial LN -> half
    ln_xs_kernel<<<(MS + 7) / 8, 256>>>(x, p_xt2, n1_w, n1_b, p_lnh);

    // 6) spatial qkv -> half  (A rows padded: MSP/256 = 99 tiles)
    gemm_hmma<0, __half><<<dim3(3 * D / 128, MSP / 256), 256, GEMM_SMEM>>>(MS, 3 * D, D, p_lnh, w_sqkv, nullptr, nullptr, p_qkvh, nullptr);

    // 7) spatial attention -> half
    attn_s_mma<<<dim3(Bn * Tt, NHh), 128, ATTN_SMEM>>>(p_qkvh, p_atth);

    // 8) spatial proj, fused x_new scatter
    gemm_hmma<4, float><<<dim3(D / 128, MSP / 256), 256, GEMM_SMEM>>>(MS, D, D, p_atth, w_sproj, s_proj_b, p_xt2, p_xnew, p_clsb);

    // 9) finish x_new cls rows + final LN
    ln_build<<<(MX + 7) / 8, 256>>>(x, p_xnew, p_clsb, n2_w, n2_b, p_xnew, p_lnh);

    // 10) fc1 + gelu -> half hid
    gemm_hmma<3, __half><<<dim3(HID / 128, MSP / 256), 256, GEMM_SMEM>>>(MXP, HID, D, p_lnh, w_fc1, fc1_b, nullptr, p_hidh, nullptr);

    // 11) fc2 + residual -> out
    gemm_hmma<2, float><<<dim3(D / 128, MSP / 256), 256, GEMM_SMEM>>>(MX, D, HID, p_hidh, w_fc2, fc2_b, p_xnew, out, nullptr);
}